// round 3
// baseline (speedup 1.0000x reference)
#include <cuda_runtime.h>

#define NN   50000
#define DD   128
#define NV4  (DD / 4)          // 32 float4 per row
#define NNZ_CAP 800000

// ---- static scratch (allocation-free rule: __device__ globals) ----
__device__ float g_bufA[NN * DD];
__device__ float g_bufB[NN * DD];
__device__ float g_bufC[NN * DD];
__device__ int   g_cnt[NN];
__device__ int   g_rptr[NN + 1];
__device__ int   g_cursor[NN];
__device__ int2  g_edges[NNZ_CAP];   // {col, val-as-int}

// ---------------- CSR build ----------------
__global__ void hist_kernel(const int* __restrict__ rows, int nnz) {
    int i = blockIdx.x * blockDim.x + threadIdx.x;
    if (i < nnz) atomicAdd(&g_cnt[rows[i]], 1);
}

__global__ void scan_kernel(int nnz) {
    __shared__ int sh[1024];
    const int t  = threadIdx.x;
    const int CH = (NN + 1023) / 1024;
    const int base = t * CH;

    int sum = 0;
    #pragma unroll 4
    for (int i = 0; i < CH; i++) {
        int idx = base + i;
        if (idx < NN) sum += g_cnt[idx];
    }
    sh[t] = sum;
    __syncthreads();

    // Hillis-Steele inclusive scan over 1024 partials
    for (int d = 1; d < 1024; d <<= 1) {
        int v = (t >= d) ? sh[t - d] : 0;
        __syncthreads();
        sh[t] += v;
        __syncthreads();
    }

    int off = sh[t] - sum;   // exclusive prefix for this chunk
    for (int i = 0; i < CH; i++) {
        int idx = base + i;
        if (idx < NN) {
            g_rptr[idx]   = off;
            g_cursor[idx] = off;
            off += g_cnt[idx];
        }
    }
    if (t == 1023) g_rptr[NN] = nnz;
}

__global__ void scatter_kernel(const int* __restrict__ rows,
                               const int* __restrict__ cols,
                               const float* __restrict__ vals, int nnz) {
    int i = blockIdx.x * blockDim.x + threadIdx.x;
    if (i < nnz) {
        int r = rows[i];
        int p = atomicAdd(&g_cursor[r], 1);
        g_edges[p] = make_int2(cols[i], __float_as_int(vals[i]));
    }
}

// ---------------- fused Chebyshev kernels ----------------
// warp per row; lane owns one float4 (4 feature columns)

__device__ __forceinline__ float4 spmm_row(const float4* __restrict__ Tc4,
                                           int s, int e, int lane) {
    float4 a = make_float4(0.f, 0.f, 0.f, 0.f);
    int i = s;
    // unroll-by-2 to raise MLP on the L2 gathers
    for (; i + 1 < e; i += 2) {
        int2 e0 = __ldg(&g_edges[i]);
        int2 e1 = __ldg(&g_edges[i + 1]);
        float4 x0 = __ldg(&Tc4[e0.x * NV4 + lane]);
        float4 x1 = __ldg(&Tc4[e1.x * NV4 + lane]);
        float v0 = __int_as_float(e0.y);
        float v1 = __int_as_float(e1.y);
        a.x += v0 * x0.x; a.y += v0 * x0.y; a.z += v0 * x0.z; a.w += v0 * x0.w;
        a.x += v1 * x1.x; a.y += v1 * x1.y; a.z += v1 * x1.z; a.w += v1 * x1.w;
    }
    if (i < e) {
        int2 e0 = __ldg(&g_edges[i]);
        float4 x0 = __ldg(&Tc4[e0.x * NV4 + lane]);
        float v0 = __int_as_float(e0.y);
        a.x += v0 * x0.x; a.y += v0 * x0.y; a.z += v0 * x0.z; a.w += v0 * x0.w;
    }
    return a;
}

// T1 = L @ X ; acc = c0*X + c1*T1
__global__ void cheb_first(const float* __restrict__ X,
                           float* __restrict__ T1,
                           float* __restrict__ acc,
                           const float* __restrict__ coeffs) {
    int gw   = (blockIdx.x * blockDim.x + threadIdx.x) >> 5;
    int lane = threadIdx.x & 31;
    if (gw >= NN) return;
    int s = g_rptr[gw], e = g_rptr[gw + 1];

    const float4* Xv = (const float4*)X;
    float4 a = spmm_row(Xv, s, e, lane);

    int idx = gw * NV4 + lane;
    ((float4*)T1)[idx] = a;

    float4 x0 = __ldg(&Xv[idx]);
    float c0 = coeffs[0], c1 = coeffs[1];
    float4 o;
    o.x = c0 * x0.x + c1 * a.x;
    o.y = c0 * x0.y + c1 * a.y;
    o.z = c0 * x0.z + c1 * a.z;
    o.w = c0 * x0.w + c1 * a.w;
    ((float4*)acc)[idx] = o;
}

// Tk = 2*(L @ Tc) - Tp ; acc += ck*Tk ; Tn = Tk
__global__ void cheb_step(const float* __restrict__ Tc,
                          const float* __restrict__ Tp,
                          float* __restrict__ Tn,
                          float* __restrict__ acc,
                          const float* __restrict__ coeffs, int k) {
    int gw   = (blockIdx.x * blockDim.x + threadIdx.x) >> 5;
    int lane = threadIdx.x & 31;
    if (gw >= NN) return;
    int s = g_rptr[gw], e = g_rptr[gw + 1];

    const float4* Tc4 = (const float4*)Tc;
    float4 a = spmm_row(Tc4, s, e, lane);

    int idx = gw * NV4 + lane;
    float4 tp = __ldg(&((const float4*)Tp)[idx]);
    float4 tk;
    tk.x = 2.f * a.x - tp.x;
    tk.y = 2.f * a.y - tp.y;
    tk.z = 2.f * a.z - tp.z;
    tk.w = 2.f * a.w - tp.w;
    ((float4*)Tn)[idx] = tk;

    float ck = coeffs[k];
    float4* accv = (float4*)acc;
    float4 av = accv[idx];
    av.x += ck * tk.x;
    av.y += ck * tk.y;
    av.z += ck * tk.z;
    av.w += ck * tk.w;
    accv[idx] = av;
}

// ---------------- launch ----------------
extern "C" void kernel_launch(void* const* d_in, const int* in_sizes, int n_in,
                              void* d_out, int out_size) {
    const int*   rows   = (const int*)d_in[0];
    const int*   cols   = (const int*)d_in[1];
    const float* vals   = (const float*)d_in[2];
    const float* X      = (const float*)d_in[3];
    const float* coeffs = (const float*)d_in[4];
    const int nnz = in_sizes[0];
    const int M   = in_sizes[4];

    void* p;
    float *pA, *pB, *pC;
    int* pcnt;
    cudaGetSymbolAddress(&p, g_bufA); pA = (float*)p;
    cudaGetSymbolAddress(&p, g_bufB); pB = (float*)p;
    cudaGetSymbolAddress(&p, g_bufC); pC = (float*)p;
    cudaGetSymbolAddress(&p, g_cnt);  pcnt = (int*)p;

    // ---- CSR build (in-graph, re-done every replay) ----
    cudaMemsetAsync(pcnt, 0, NN * sizeof(int));
    hist_kernel<<<(nnz + 255) / 256, 256>>>(rows, nnz);
    scan_kernel<<<1, 1024>>>(nnz);
    scatter_kernel<<<(nnz + 255) / 256, 256>>>(rows, cols, vals, nnz);

    // ---- Chebyshev recurrence ----
    const int threads = 256;                 // 8 rows per block
    const int rowsPerBlk = threads / 32;
    const int grid = (NN + rowsPerBlk - 1) / rowsPerBlk;
    float* accp = (float*)d_out;

    cheb_first<<<grid, threads>>>(X, pA, accp, coeffs);

    const float* prev = X;
    float* curr = pA;
    float* nxt  = pB;
    float* spare = pC;

    for (int k = 2; k < M; k++) {
        cheb_step<<<grid, threads>>>(curr, prev, nxt, accp, coeffs, k);
        float* recycled = (k == 2) ? spare : (float*)prev;
        prev = curr;
        curr = nxt;
        nxt  = recycled;
    }
}

// round 5
// speedup vs baseline: 1.6063x; 1.6063x over previous
#include <cuda_runtime.h>
#include <cuda_fp16.h>

#define NN   50000
#define DD   128
#define NNZ_CAP 800000

// ---- static scratch (allocation-free rule: __device__ globals) ----
__device__ __half g_h0[NN * DD];     // fp16 T buffers (rotating)
__device__ __half g_hA[NN * DD];
__device__ __half g_hB[NN * DD];
__device__ int   g_cnt[NN];
__device__ int   g_rptr[NN + 1];
__device__ int   g_cursor[NN];
__device__ int2  g_edges[NNZ_CAP];   // {col, val-as-int}

// ---------------- CSR build ----------------
__global__ void hist_kernel(const int* __restrict__ rows, int nnz) {
    int i = blockIdx.x * blockDim.x + threadIdx.x;
    if (i < nnz) atomicAdd(&g_cnt[rows[i]], 1);
}

__global__ void scan_kernel(int nnz) {
    __shared__ int sh[1024];
    const int t  = threadIdx.x;
    const int CH = (NN + 1023) / 1024;
    const int base = t * CH;

    int sum = 0;
    #pragma unroll 4
    for (int i = 0; i < CH; i++) {
        int idx = base + i;
        if (idx < NN) sum += g_cnt[idx];
    }
    sh[t] = sum;
    __syncthreads();

    for (int d = 1; d < 1024; d <<= 1) {
        int v = (t >= d) ? sh[t - d] : 0;
        __syncthreads();
        sh[t] += v;
        __syncthreads();
    }

    int off = sh[t] - sum;   // exclusive prefix for this chunk
    for (int i = 0; i < CH; i++) {
        int idx = base + i;
        if (idx < NN) {
            g_rptr[idx]   = off;
            g_cursor[idx] = off;
            off += g_cnt[idx];
        }
    }
    if (t == 1023) g_rptr[NN] = nnz;
}

__global__ void scatter_kernel(const int* __restrict__ rows,
                               const int* __restrict__ cols,
                               const float* __restrict__ vals, int nnz) {
    int i = blockIdx.x * blockDim.x + threadIdx.x;
    if (i < nnz) {
        int r = rows[i];
        int p = atomicAdd(&g_cursor[r], 1);
        g_edges[p] = make_int2(cols[i], __float_as_int(vals[i]));
    }
}

// ---------------- fp32 -> fp16 convert (X -> T0 buffer) ----------------
__global__ void convert_kernel(const float* __restrict__ X, __half* __restrict__ H) {
    int i = blockIdx.x * blockDim.x + threadIdx.x;          // 4 elems per thread
    if (i < NN * DD / 4) {
        float4 v = __ldg(&((const float4*)X)[i]);
        __half2 lo = __floats2half2_rn(v.x, v.y);
        __half2 hi = __floats2half2_rn(v.z, v.w);
        uint2 r;
        r.x = *(unsigned int*)&lo;
        r.y = *(unsigned int*)&hi;
        ((uint2*)H)[i] = r;
    }
}

// ---------------- fused Chebyshev kernels ----------------
// warp per row; lane owns 4 feature columns (8B fp16 per lane)

__device__ __forceinline__ void fma_h(float4& a, uint2 r, float v) {
    float2 lo = __half22float2(*(const __half2*)&r.x);
    float2 hi = __half22float2(*(const __half2*)&r.y);
    a.x += v * lo.x; a.y += v * lo.y; a.z += v * hi.x; a.w += v * hi.y;
}

__device__ __forceinline__ uint2 pack_h(float4 t) {
    __half2 lo = __floats2half2_rn(t.x, t.y);
    __half2 hi = __floats2half2_rn(t.z, t.w);
    uint2 r;
    r.x = *(unsigned int*)&lo;
    r.y = *(unsigned int*)&hi;
    return r;
}

__device__ __forceinline__ float4 spmm_row_h(const __half* __restrict__ T,
                                             int s, int e, int lane) {
    float4 a = make_float4(0.f, 0.f, 0.f, 0.f);
    const uint2* Tv = (const uint2*)T;    // 4 halves per uint2; row stride = DD/4 = 32
    int i = s;
    // unroll-by-4: keep 4 gathers + 4 edge loads outstanding (MLP)
    for (; i + 3 < e; i += 4) {
        int2 e0 = __ldg(&g_edges[i]);
        int2 e1 = __ldg(&g_edges[i + 1]);
        int2 e2 = __ldg(&g_edges[i + 2]);
        int2 e3 = __ldg(&g_edges[i + 3]);
        uint2 r0 = __ldg(&Tv[e0.x * 32 + lane]);
        uint2 r1 = __ldg(&Tv[e1.x * 32 + lane]);
        uint2 r2 = __ldg(&Tv[e2.x * 32 + lane]);
        uint2 r3 = __ldg(&Tv[e3.x * 32 + lane]);
        fma_h(a, r0, __int_as_float(e0.y));
        fma_h(a, r1, __int_as_float(e1.y));
        fma_h(a, r2, __int_as_float(e2.y));
        fma_h(a, r3, __int_as_float(e3.y));
    }
    for (; i < e; i++) {
        int2 e0 = __ldg(&g_edges[i]);
        uint2 r0 = __ldg(&Tv[e0.x * 32 + lane]);
        fma_h(a, r0, __int_as_float(e0.y));
    }
    return a;
}

// T1 = L @ X(h) ; acc = c0*X + c1*T1 ; store T1 fp16
__global__ void cheb_first(const __half* __restrict__ Xh,
                           const float* __restrict__ X,
                           __half* __restrict__ T1,
                           float* __restrict__ acc,
                           const float* __restrict__ coeffs) {
    int gw   = (blockIdx.x * blockDim.x + threadIdx.x) >> 5;
    int lane = threadIdx.x & 31;
    if (gw >= NN) return;
    int s = g_rptr[gw], e = g_rptr[gw + 1];

    float4 a = spmm_row_h(Xh, s, e, lane);

    int idx = gw * 32 + lane;
    ((uint2*)T1)[idx] = pack_h(a);

    float4 x0 = __ldg(&((const float4*)X)[idx]);
    float c0 = coeffs[0], c1 = coeffs[1];
    float4 o;
    o.x = c0 * x0.x + c1 * a.x;
    o.y = c0 * x0.y + c1 * a.y;
    o.z = c0 * x0.z + c1 * a.z;
    o.w = c0 * x0.w + c1 * a.w;
    ((float4*)acc)[idx] = o;
}

// Tk = 2*(L @ Tc) - Tp ; acc += ck*Tk ; store Tk fp16
__global__ void cheb_step(const __half* __restrict__ Tc,
                          const __half* __restrict__ Tp,
                          __half* __restrict__ Tn,
                          float* __restrict__ acc,
                          const float* __restrict__ coeffs, int k) {
    int gw   = (blockIdx.x * blockDim.x + threadIdx.x) >> 5;
    int lane = threadIdx.x & 31;
    if (gw >= NN) return;
    int s = g_rptr[gw], e = g_rptr[gw + 1];

    float4 a = spmm_row_h(Tc, s, e, lane);

    int idx = gw * 32 + lane;
    uint2 tpr = __ldg(&((const uint2*)Tp)[idx]);
    float2 tplo = __half22float2(*(const __half2*)&tpr.x);
    float2 tphi = __half22float2(*(const __half2*)&tpr.y);

    float4 tk;
    tk.x = 2.f * a.x - tplo.x;
    tk.y = 2.f * a.y - tplo.y;
    tk.z = 2.f * a.z - tphi.x;
    tk.w = 2.f * a.w - tphi.y;
    ((uint2*)Tn)[idx] = pack_h(tk);

    float ck = coeffs[k];
    float4* accv = (float4*)acc;
    float4 av = accv[idx];
    av.x += ck * tk.x;
    av.y += ck * tk.y;
    av.z += ck * tk.z;
    av.w += ck * tk.w;
    accv[idx] = av;
}

// ---------------- launch ----------------
extern "C" void kernel_launch(void* const* d_in, const int* in_sizes, int n_in,
                              void* d_out, int out_size) {
    const int*   rows   = (const int*)d_in[0];
    const int*   cols   = (const int*)d_in[1];
    const float* vals   = (const float*)d_in[2];
    const float* X      = (const float*)d_in[3];
    const float* coeffs = (const float*)d_in[4];
    const int nnz = in_sizes[0];
    const int M   = in_sizes[4];

    void* p;
    __half *h0, *hA, *hB;
    int* pcnt;
    cudaGetSymbolAddress(&p, g_h0);  h0 = (__half*)p;
    cudaGetSymbolAddress(&p, g_hA);  hA = (__half*)p;
    cudaGetSymbolAddress(&p, g_hB);  hB = (__half*)p;
    cudaGetSymbolAddress(&p, g_cnt); pcnt = (int*)p;

    // ---- CSR build (in-graph, re-done every replay) ----
    cudaMemsetAsync(pcnt, 0, NN * sizeof(int));
    hist_kernel<<<(nnz + 255) / 256, 256>>>(rows, nnz);
    scan_kernel<<<1, 1024>>>(nnz);
    scatter_kernel<<<(nnz + 255) / 256, 256>>>(rows, cols, vals, nnz);

    // ---- X -> fp16 T0 ----
    convert_kernel<<<(NN * DD / 4 + 255) / 256, 256>>>(X, h0);

    // ---- Chebyshev recurrence ----
    const int threads = 256;                 // 8 rows per block
    const int rowsPerBlk = threads / 32;
    const int grid = (NN + rowsPerBlk - 1) / rowsPerBlk;
    float* accp = (float*)d_out;

    cheb_first<<<grid, threads>>>(h0, X, hA, accp, coeffs);

    const __half* prev = h0;
    const __half* curr = hA;
    __half* nxt = hB;

    for (int k = 2; k < M; k++) {
        cheb_step<<<grid, threads>>>(curr, prev, nxt, accp, coeffs, k);
        __half* recycled = (__half*)prev;
        prev = curr;
        curr = nxt;
        nxt  = recycled;
    }
}

// round 6
// speedup vs baseline: 1.6070x; 1.0004x over previous
#include <cuda_runtime.h>
#include <cuda_fp16.h>

#define NN   50000
#define DD   128
#define NV2  (NN * DD / 4)      // uint2 (4 halves) per T slot = 1.6M
#define NNZ_CAP 800000
#define MCAP 32

// ---- static scratch (allocation-free rule: __device__ globals) ----
__device__ __half g_T[MCAP * NN * DD];   // all Chebyshev iterates, fp16 (slot k = T_k)
__device__ int   g_cnt[NN];
__device__ int   g_rptr[NN + 1];
__device__ int   g_cursor[NN];
__device__ int2  g_edges[NNZ_CAP];       // {col, val-as-int}

// ---------------- CSR build ----------------
__global__ void hist_kernel(const int* __restrict__ rows, int nnz) {
    int i = blockIdx.x * blockDim.x + threadIdx.x;
    if (i < nnz) atomicAdd(&g_cnt[rows[i]], 1);
}

__global__ void scan_kernel(int nnz) {
    __shared__ int sh[1024];
    const int t  = threadIdx.x;
    const int CH = (NN + 1023) / 1024;
    const int base = t * CH;

    int sum = 0;
    #pragma unroll 4
    for (int i = 0; i < CH; i++) {
        int idx = base + i;
        if (idx < NN) sum += g_cnt[idx];
    }
    sh[t] = sum;
    __syncthreads();

    for (int d = 1; d < 1024; d <<= 1) {
        int v = (t >= d) ? sh[t - d] : 0;
        __syncthreads();
        sh[t] += v;
        __syncthreads();
    }

    int off = sh[t] - sum;   // exclusive prefix for this chunk
    for (int i = 0; i < CH; i++) {
        int idx = base + i;
        if (idx < NN) {
            g_rptr[idx]   = off;
            g_cursor[idx] = off;
            off += g_cnt[idx];
        }
    }
    if (t == 1023) g_rptr[NN] = nnz;
}

__global__ void scatter_kernel(const int* __restrict__ rows,
                               const int* __restrict__ cols,
                               const float* __restrict__ vals, int nnz) {
    int i = blockIdx.x * blockDim.x + threadIdx.x;
    if (i < nnz) {
        int r = rows[i];
        int p = atomicAdd(&g_cursor[r], 1);
        g_edges[p] = make_int2(cols[i], __float_as_int(vals[i]));
    }
}

// ---------------- fp32 -> fp16 convert (X -> slot 0) ----------------
__global__ void convert_kernel(const float* __restrict__ X, __half* __restrict__ H) {
    int i = blockIdx.x * blockDim.x + threadIdx.x;          // 4 elems per thread
    if (i < NV2) {
        float4 v = __ldg(&((const float4*)X)[i]);
        __half2 lo = __floats2half2_rn(v.x, v.y);
        __half2 hi = __floats2half2_rn(v.z, v.w);
        uint2 r;
        r.x = *(unsigned int*)&lo;
        r.y = *(unsigned int*)&hi;
        ((uint2*)H)[i] = r;
    }
}

// ---------------- helpers ----------------
__device__ __forceinline__ void fma_h(float4& a, uint2 r, float v) {
    float2 lo = __half22float2(*(const __half2*)&r.x);
    float2 hi = __half22float2(*(const __half2*)&r.y);
    a.x += v * lo.x; a.y += v * lo.y; a.z += v * hi.x; a.w += v * hi.y;
}

__device__ __forceinline__ uint2 pack_h(float4 t) {
    __half2 lo = __floats2half2_rn(t.x, t.y);
    __half2 hi = __floats2half2_rn(t.z, t.w);
    uint2 r;
    r.x = *(unsigned int*)&lo;
    r.y = *(unsigned int*)&hi;
    return r;
}

__device__ __forceinline__ float4 spmm_row_h(const __half* __restrict__ T,
                                             int s, int e, int lane) {
    float4 a = make_float4(0.f, 0.f, 0.f, 0.f);
    const uint2* Tv = (const uint2*)T;    // 4 halves per uint2; row stride = 32
    int i = s;
    // unroll-by-4: keep 4 gathers + 4 edge loads outstanding (MLP)
    for (; i + 3 < e; i += 4) {
        int2 e0 = __ldg(&g_edges[i]);
        int2 e1 = __ldg(&g_edges[i + 1]);
        int2 e2 = __ldg(&g_edges[i + 2]);
        int2 e3 = __ldg(&g_edges[i + 3]);
        uint2 r0 = __ldg(&Tv[e0.x * 32 + lane]);
        uint2 r1 = __ldg(&Tv[e1.x * 32 + lane]);
        uint2 r2 = __ldg(&Tv[e2.x * 32 + lane]);
        uint2 r3 = __ldg(&Tv[e3.x * 32 + lane]);
        fma_h(a, r0, __int_as_float(e0.y));
        fma_h(a, r1, __int_as_float(e1.y));
        fma_h(a, r2, __int_as_float(e2.y));
        fma_h(a, r3, __int_as_float(e3.y));
    }
    for (; i < e; i++) {
        int2 e0 = __ldg(&g_edges[i]);
        uint2 r0 = __ldg(&Tv[e0.x * 32 + lane]);
        fma_h(a, r0, __int_as_float(e0.y));
    }
    return a;
}

// T1 = L @ T0 (slot0 -> slot1); no acc work
__global__ void cheb_first(const __half* __restrict__ T0,
                           __half* __restrict__ T1) {
    int gw   = (blockIdx.x * blockDim.x + threadIdx.x) >> 5;
    int lane = threadIdx.x & 31;
    if (gw >= NN) return;
    int s = g_rptr[gw], e = g_rptr[gw + 1];

    float4 a = spmm_row_h(T0, s, e, lane);
    ((uint2*)T1)[gw * 32 + lane] = pack_h(a);
}

// Tk = 2*(L @ Tc) - Tp  (slot k-1, slot k-2 -> slot k); no acc work
__global__ void cheb_step(const __half* __restrict__ Tc,
                          const __half* __restrict__ Tp,
                          __half* __restrict__ Tn) {
    int gw   = (blockIdx.x * blockDim.x + threadIdx.x) >> 5;
    int lane = threadIdx.x & 31;
    if (gw >= NN) return;
    int s = g_rptr[gw], e = g_rptr[gw + 1];

    float4 a = spmm_row_h(Tc, s, e, lane);

    int idx = gw * 32 + lane;
    uint2 tpr = __ldg(&((const uint2*)Tp)[idx]);
    float2 tplo = __half22float2(*(const __half2*)&tpr.x);
    float2 tphi = __half22float2(*(const __half2*)&tpr.y);

    float4 tk;
    tk.x = 2.f * a.x - tplo.x;
    tk.y = 2.f * a.y - tplo.y;
    tk.z = 2.f * a.z - tphi.x;
    tk.w = 2.f * a.w - tphi.y;
    ((uint2*)Tn)[idx] = pack_h(tk);
}

// out = sum_k coeffs[k] * T_k   (single streaming pass over all slots)
__global__ void reduce_kernel(const __half* __restrict__ T,
                              const float* __restrict__ coeffs,
                              float* __restrict__ out, int M) {
    int i = blockIdx.x * blockDim.x + threadIdx.x;
    if (i >= NV2) return;
    const uint2* base = (const uint2*)T;
    float4 a = make_float4(0.f, 0.f, 0.f, 0.f);
    int k = 0;
    for (; k + 3 < M; k += 4) {
        uint2 r0 = __ldg(&base[(size_t)(k + 0) * NV2 + i]);
        uint2 r1 = __ldg(&base[(size_t)(k + 1) * NV2 + i]);
        uint2 r2 = __ldg(&base[(size_t)(k + 2) * NV2 + i]);
        uint2 r3 = __ldg(&base[(size_t)(k + 3) * NV2 + i]);
        fma_h(a, r0, __ldg(&coeffs[k + 0]));
        fma_h(a, r1, __ldg(&coeffs[k + 1]));
        fma_h(a, r2, __ldg(&coeffs[k + 2]));
        fma_h(a, r3, __ldg(&coeffs[k + 3]));
    }
    for (; k < M; k++) {
        uint2 r = __ldg(&base[(size_t)k * NV2 + i]);
        fma_h(a, r, __ldg(&coeffs[k]));
    }
    ((float4*)out)[i] = a;
}

// ---------------- launch ----------------
extern "C" void kernel_launch(void* const* d_in, const int* in_sizes, int n_in,
                              void* d_out, int out_size) {
    const int*   rows   = (const int*)d_in[0];
    const int*   cols   = (const int*)d_in[1];
    const float* vals   = (const float*)d_in[2];
    const float* X      = (const float*)d_in[3];
    const float* coeffs = (const float*)d_in[4];
    const int nnz = in_sizes[0];
    const int M   = in_sizes[4];

    void* p;
    __half* T;
    int* pcnt;
    cudaGetSymbolAddress(&p, g_T);   T = (__half*)p;
    cudaGetSymbolAddress(&p, g_cnt); pcnt = (int*)p;

    const size_t SLOT = (size_t)NN * DD;

    // ---- CSR build (in-graph, re-done every replay) ----
    cudaMemsetAsync(pcnt, 0, NN * sizeof(int));
    hist_kernel<<<(nnz + 255) / 256, 256>>>(rows, nnz);
    scan_kernel<<<1, 1024>>>(nnz);
    scatter_kernel<<<(nnz + 255) / 256, 256>>>(rows, cols, vals, nnz);

    // ---- X -> fp16 slot 0 ----
    convert_kernel<<<(NV2 + 255) / 256, 256>>>(X, T);

    // ---- Chebyshev recurrence: slot k = T_k ----
    const int threads = 256;                 // 8 rows per block
    const int rowsPerBlk = threads / 32;
    const int grid = (NN + rowsPerBlk - 1) / rowsPerBlk;

    cheb_first<<<grid, threads>>>(T, T + SLOT);
    for (int k = 2; k < M; k++) {
        cheb_step<<<grid, threads>>>(T + (size_t)(k - 1) * SLOT,
                                     T + (size_t)(k - 2) * SLOT,
                                     T + (size_t)k * SLOT);
    }

    // ---- final weighted reduction ----
    reduce_kernel<<<(NV2 + 255) / 256, 256>>>(T, coeffs, (float*)d_out, M);
}